// round 9
// baseline (speedup 1.0000x reference)
#include <cuda_runtime.h>

#define TPB 256
#define RPT 8
#define TILE (TPB * RPT)

#define EPSF   1e-12f
#define TOLF   1e-6f
#define LAMF   10000.0f
#define INVLAM (1.0f / 10000.0f)

// Sign of phi(t) = (p - t*A)*U_MAX - (b + t/LAM)*sqrt(max(N - 2tp + t^2 A, EPS))
// without the sqrt:  phi > 0  <=>  L > R*sqrt(S), S >= EPS > 0.
__device__ __forceinline__ bool phi_pos(float t, float A, float p, float N, float b) {
    float S = fmaf(t, fmaf(t, A, -2.0f * p), N);
    S = fmaxf(S, EPSF);
    float L = fmaf(-t, A, p);          // p - t*A   (U_MAX = 1)
    float R = fmaf(t, INVLAM, b);      // b + t/LAM
    float L2  = L * L;
    float R2S = (R * R) * S;
    // R <  0: R*sqrt(S) <= 0, so phi>0 if L>=0, else compare magnitudes.
    // R >= 0: need L>0 and L^2 > R^2 S.
    return (R < 0.0f) ? ((L >= 0.0f) || (L2 < R2S))
                      : ((L > 0.0f) && (L2 > R2S));
}

__global__ __launch_bounds__(TPB)
void cbf_kernel(const float* __restrict__ u_nom,
                const float* __restrict__ obs,
                float* __restrict__ out,
                int B) {
    __shared__ int scnt;
    __shared__ int sidx[TILE];
    if (threadIdx.x == 0) scnt = 0;
    __syncthreads();

    const float2* __restrict__ un2  = (const float2*)u_nom;
    float2* __restrict__       out2 = (float2*)out;
    const int base = blockIdx.x * TILE;
    const int lane = threadIdx.x & 31;

    // ---------------- Phase A: stream rows, resolve cases 1 & 2, queue case 3 ----
    #pragma unroll
    for (int r = 0; r < RPT; ++r) {
        int row = base + r * TPB + (int)threadIdx.x;
        bool valid = (row < B);
        bool need3 = false;
        if (valid) {
            float2 un = un2[row];
            const float* o = obs + (size_t)row * 6;
            float2 pr = *(const float2*)(o + 2);   // p_rel
            float2 vh = *(const float2*)(o + 4);   // v_human
            float ax = -2.0f * pr.x, ay = -2.0f * pr.y;
            float h  = fmaf(pr.x, pr.x, pr.y * pr.y) - 1.0f;             // |p|^2 - SAFE^2
            float bb = 2.0f * h - 2.0f * fmaf(pr.x, vh.x, pr.y * vh.y);  // ALPHA*h - 2 p.v
            float A  = fmaf(ax, ax, ay * ay);
            float p  = fmaf(ax, un.x, ay * un.y);
            float N  = fmaf(un.x, un.x, un.y * un.y);
            float n  = sqrtf(fmaxf(N, EPSF));
            float sc = fminf(1.0f, 1.0f / n);
            if (p * sc <= bb + TOLF) {
                out2[row] = make_float2(un.x * sc, un.y * sc);           // case 1
            } else {
                float t2  = (LAMF * (p - bb)) / fmaf(LAMF, A, 1.0f);
                float u2x = fmaf(-t2, ax, un.x);
                float u2y = fmaf(-t2, ay, un.y);
                float nu2 = fmaf(u2x, u2x, u2y * u2y);
                if (t2 >= -TOLF && nu2 <= 1.0f + TOLF) {
                    out2[row] = make_float2(u2x, u2y);                   // case 2
                } else {
                    need3 = true;                                        // case 3
                }
            }
        }
        // warp-aggregated push into shared queue
        unsigned m = __ballot_sync(0xffffffffu, need3);
        if (m) {
            int leader = __ffs(m) - 1;
            int pos = 0;
            if (lane == leader) pos = atomicAdd(&scnt, __popc(m));
            pos = __shfl_sync(0xffffffffu, pos, leader);
            if (need3) sidx[pos + __popc(m & ((1u << lane) - 1u))] = row;
        }
    }
    __syncthreads();

    // ---------------- Phase B: dense solver over compacted case-3 rows ----------
    const int cnt   = scnt;
    const int iters = (cnt + TPB - 1) / TPB;
    for (int it = 0; it < iters; ++it) {
        int  j   = it * TPB + (int)threadIdx.x;
        bool act = (j < cnt);
        int  row = act ? sidx[j] : 0;

        // dummy values make phi(t)<0 immediately for inactive lanes
        float A = 1.0f, p = 0.0f, N = 1.0f, bb = 1.0f;
        float ax = 0.0f, ay = 0.0f, unx = 0.0f, uny = 0.0f;
        if (act) {
            float2 un = un2[row];
            const float* o = obs + (size_t)row * 6;
            float2 pr = *(const float2*)(o + 2);
            float2 vh = *(const float2*)(o + 4);
            ax = -2.0f * pr.x; ay = -2.0f * pr.y;
            unx = un.x; uny = un.y;
            float h = fmaf(pr.x, pr.x, pr.y * pr.y) - 1.0f;
            bb = 2.0f * h - 2.0f * fmaf(pr.x, vh.x, pr.y * vh.y);
            A  = fmaf(ax, ax, ay * ay);
            p  = fmaf(ax, unx, ay * uny);
            N  = fmaf(unx, unx, uny * uny);
        }

        // doubling (warp-coherent early exit, max 40 like the reference)
        float th = 1.0f;
        for (int i = 0; i < 40; ++i) {
            bool pos = phi_pos(th, A, p, N, bb);
            if (__all_sync(0xffffffffu, !pos)) break;
            th = pos ? 2.0f * th : th;
        }

        // 60 sqrt-free bisections
        float lo = 0.0f, hi = th;
        #pragma unroll 4
        for (int i = 0; i < 60; ++i) {
            float mid = 0.5f * (lo + hi);
            bool  pos = phi_pos(mid, A, p, N, bb);
            lo = pos ? mid : lo;
            hi = pos ? hi : mid;
        }
        float t3 = 0.5f * (lo + hi);

        // 3 Newton polish steps (exact reference formulas)
        #pragma unroll
        for (int i = 0; i < 3; ++i) {
            float S   = fmaxf(fmaf(t3, fmaf(t3, A, -2.0f * p), N), EPSF);
            float nrm = sqrtf(S);
            float f   = fmaf(-t3, A, p) - fmaf(t3, INVLAM, bb) * nrm;
            float df  = -A - nrm * INVLAM - fmaf(t3, INVLAM, bb) * fmaf(t3, A, -p) / nrm;
            df = (fabsf(df) > 1e-8f) ? df : -1e-8f;
            t3 = t3 - f / df;
        }

        float S3   = fmaxf(fmaf(t3, fmaf(t3, A, -2.0f * p), N), EPSF);
        float nrm3 = sqrtf(S3);
        float k3   = fmaxf(nrm3, 1.0f);     // U_MAX = 1
        float inv  = 1.0f / k3;
        if (act) {
            out2[row] = make_float2(fmaf(-t3, ax, unx) * inv,
                                    fmaf(-t3, ay, uny) * inv);
        }
    }
}

extern "C" void kernel_launch(void* const* d_in, const int* in_sizes, int n_in,
                              void* d_out, int out_size) {
    const float* u_nom = (const float*)d_in[0];
    const float* obs   = (const float*)d_in[1];
    float*       out   = (float*)d_out;
    int B = in_sizes[0] / 2;
    int grid = (B + TILE - 1) / TILE;
    cbf_kernel<<<grid, TPB>>>(u_nom, obs, out, B);
}

// round 13
// speedup vs baseline: 1.5577x; 1.5577x over previous
#include <cuda_runtime.h>

#define TPB 256
#define RPT 8
#define TILE (TPB * RPT)

#define EPSF   1e-12f
#define TOLF   1e-6f
#define LAMF   10000.0f
#define INVLAM (1.0f / 10000.0f)

// Sign of phi(t) = (p - t*A) - (b + t/LAM)*sqrt(S),  S = N - 2tp + t^2 A.
// Let L = p - tA, R = b + t/LAM, D = L^2 - R^2*S = (L - R sqrt S)(L + R sqrt S).
// If D>0: |L| > |R|sqrt(S)  -> sign(phi) = sign(L).
// If D<0: |R|sqrt(S) > |L|  -> sign(phi) = sign(-R).
// (No clamp needed: S<0 numerically => D >= L^2 >= 0 => sign(L), matching the
//  EPS-clamped reference to within the Newton polish's basin.)
__device__ __forceinline__ bool phi_pos(float t, float A, float p, float N, float b) {
    float S = fmaf(t, fmaf(t, A, -2.0f * p), N);
    float L = fmaf(-t, A, p);
    float R = fmaf(t, INVLAM, b);
    float D = fmaf(L, L, -(R * R) * S);
    return (D > 0.0f) ? (L > 0.0f) : ((D < 0.0f) && (R < 0.0f));
}

__global__ __launch_bounds__(TPB)
void cbf_kernel(const float* __restrict__ u_nom,
                const float* __restrict__ obs,
                float* __restrict__ out,
                int B) {
    __shared__ int scnt;
    __shared__ int sidx[TILE];
    if (threadIdx.x == 0) scnt = 0;
    __syncthreads();

    const float2* __restrict__ un2  = (const float2*)u_nom;
    float2* __restrict__       out2 = (float2*)out;
    const int base = blockIdx.x * TILE;
    const int lane = threadIdx.x & 31;

    // ---------------- Phase A: stream rows, resolve cases 1 & 2, queue case 3 ----
    #pragma unroll
    for (int r = 0; r < RPT; ++r) {
        int row = base + r * TPB + (int)threadIdx.x;
        bool valid = (row < B);
        bool need3 = false;
        if (valid) {
            float2 un = un2[row];
            const float* o = obs + (size_t)row * 6;
            float2 pr = *(const float2*)(o + 2);   // p_rel
            float2 vh = *(const float2*)(o + 4);   // v_human
            float ax = -2.0f * pr.x, ay = -2.0f * pr.y;
            float h  = fmaf(pr.x, pr.x, pr.y * pr.y) - 1.0f;             // |p|^2 - SAFE^2
            float bb = 2.0f * h - 2.0f * fmaf(pr.x, vh.x, pr.y * vh.y);  // ALPHA*h - 2 p.v
            float A  = fmaf(ax, ax, ay * ay);
            float p  = fmaf(ax, un.x, ay * un.y);
            float N  = fmaf(un.x, un.x, un.y * un.y);
            float sc = fminf(1.0f, __frsqrt_rn(fmaxf(N, EPSF)));
            if (p * sc <= bb + TOLF) {
                out2[row] = make_float2(un.x * sc, un.y * sc);           // case 1
            } else {
                float t2  = __fdividef(LAMF * (p - bb), fmaf(LAMF, A, 1.0f));
                float u2x = fmaf(-t2, ax, un.x);
                float u2y = fmaf(-t2, ay, un.y);
                float nu2 = fmaf(u2x, u2x, u2y * u2y);
                if (t2 >= -TOLF && nu2 <= 1.0f + TOLF) {
                    out2[row] = make_float2(u2x, u2y);                   // case 2
                } else {
                    need3 = true;                                        // case 3
                }
            }
        }
        // warp-aggregated push into shared queue
        unsigned m = __ballot_sync(0xffffffffu, need3);
        if (m) {
            int leader = __ffs(m) - 1;
            int pos = 0;
            if (lane == leader) pos = atomicAdd(&scnt, __popc(m));
            pos = __shfl_sync(0xffffffffu, pos, leader);
            if (need3) sidx[pos + __popc(m & ((1u << lane) - 1u))] = row;
        }
    }
    __syncthreads();

    // ---------------- Phase B: dense solver over compacted case-3 rows ----------
    const int cnt   = scnt;
    const int iters = (cnt + TPB - 1) / TPB;
    for (int it = 0; it < iters; ++it) {
        int  j   = it * TPB + (int)threadIdx.x;
        bool act = (j < cnt);
        int  row = act ? sidx[j] : 0;

        // dummy values make phi(t)<=0 immediately for inactive lanes
        float A = 1.0f, p = 0.0f, N = 1.0f, bb = 1.0f;
        float ax = 0.0f, ay = 0.0f, unx = 0.0f, uny = 0.0f;
        if (act) {
            float2 un = un2[row];
            const float* o = obs + (size_t)row * 6;
            float2 pr = *(const float2*)(o + 2);
            float2 vh = *(const float2*)(o + 4);
            ax = -2.0f * pr.x; ay = -2.0f * pr.y;
            unx = un.x; uny = un.y;
            float h = fmaf(pr.x, pr.x, pr.y * pr.y) - 1.0f;
            bb = 2.0f * h - 2.0f * fmaf(pr.x, vh.x, pr.y * vh.y);
            A  = fmaf(ax, ax, ay * ay);
            p  = fmaf(ax, unx, ay * uny);
            N  = fmaf(unx, unx, uny * uny);
        }

        // doubling with bracket tracking (warp-coherent early exit, max 40)
        float lo = 0.0f, hi = 1.0f;
        for (int i = 0; i < 40; ++i) {
            bool pos = phi_pos(hi, A, p, N, bb);
            if (__all_sync(0xffffffffu, !pos)) break;
            if (pos) { lo = hi; hi = 2.0f * hi; }
        }

        // 20 sqrt-free bisections on the tight bracket [lo, hi]
        #pragma unroll 5
        for (int i = 0; i < 20; ++i) {
            float mid = 0.5f * (lo + hi);
            bool  pos = phi_pos(mid, A, p, N, bb);
            lo = pos ? mid : lo;
            hi = pos ? hi : mid;
        }
        float t3 = 0.5f * (lo + hi);

        // 4 Newton polish steps (reference formulas; fast div, ample precision)
        #pragma unroll
        for (int i = 0; i < 4; ++i) {
            float S   = fmaxf(fmaf(t3, fmaf(t3, A, -2.0f * p), N), EPSF);
            float nrm = sqrtf(S);
            float Rr  = fmaf(t3, INVLAM, bb);
            float f   = fmaf(-t3, A, p) - Rr * nrm;
            float df  = -A - nrm * INVLAM - Rr * __fdividef(fmaf(t3, A, -p), nrm);
            df = (fabsf(df) > 1e-8f) ? df : -1e-8f;
            t3 = t3 - __fdividef(f, df);
        }

        float S3   = fmaxf(fmaf(t3, fmaf(t3, A, -2.0f * p), N), EPSF);
        float nrm3 = sqrtf(S3);
        float inv  = (nrm3 > 1.0f) ? __fdividef(1.0f, nrm3) : 1.0f;
        if (act) {
            out2[row] = make_float2(fmaf(-t3, ax, unx) * inv,
                                    fmaf(-t3, ay, uny) * inv);
        }
    }
}

extern "C" void kernel_launch(void* const* d_in, const int* in_sizes, int n_in,
                              void* d_out, int out_size) {
    const float* u_nom = (const float*)d_in[0];
    const float* obs   = (const float*)d_in[1];
    float*       out   = (float*)d_out;
    int B = in_sizes[0] / 2;
    int grid = (B + TILE - 1) / TILE;
    cbf_kernel<<<grid, TPB>>>(u_nom, obs, out, B);
}